// round 1
// baseline (speedup 1.0000x reference)
#include <cuda_runtime.h>
#include <cstddef>

// Problem constants (fixed by the reference)
#define N_GRID  64
#define N_SITES 4096            // 64*64
#define BATCH   512
#define THREADS 256
#define SITES_PER_THREAD (N_SITES / THREADS)   // 16

// Coefficient scratch: [0..4095] = unary, [4096..8191] = J_right, [8192..12287] = J_down
__device__ float g_coef[3 * N_SITES];

// Kernel 1: gather the sparse coupling structure out of the dense binary/mask.
// Only ~2 entries per row of the 4096x4096 matrices are ever nonzero.
__global__ void gather_coef_kernel(const float* __restrict__ unary,
                                   const float* __restrict__ binary,
                                   const float* __restrict__ mask) {
    int i = blockIdx.x * blockDim.x + threadIdx.x;
    if (i >= N_SITES) return;

    g_coef[i] = unary[i];

    float jr = 0.0f;
    float jd = 0.0f;

    // right neighbor: j = i+1, valid when i is not at the end of a grid row
    if (((i + 1) % N_GRID) != 0 && (i + 1) < N_SITES) {
        size_t off = (size_t)i * N_SITES + (i + 1);
        jr = binary[off] * mask[off];
    }
    // down neighbor: j = i + N_GRID
    if ((i + N_GRID) < N_SITES) {
        size_t off = (size_t)i * N_SITES + (i + N_GRID);
        jd = binary[off] * mask[off];
    }

    g_coef[N_SITES + i]     = jr;
    g_coef[2 * N_SITES + i] = jd;
}

// Kernel 2: one block per batch row. Load the x row to shared (padded so
// xs[i+64] is always in-bounds; the zero J coefficients kill boundary terms),
// accumulate u_i*x_i + Jr_i*x_i*x_{i+1} + Jd_i*x_i*x_{i+64}, block-reduce.
__global__ __launch_bounds__(THREADS, 1)
void ising_energy_kernel(const float* __restrict__ x, float* __restrict__ out) {
    __shared__ float xs[N_SITES + N_GRID];      // +64 zero padding
    __shared__ float warp_sums[THREADS / 32];

    const int tid = threadIdx.x;
    const int b   = blockIdx.x;

    // Vectorized load of the 4096-float row: 4 float4 per thread.
    const float4* xrow = reinterpret_cast<const float4*>(x + (size_t)b * N_SITES);
    float4* xs4 = reinterpret_cast<float4*>(xs);
#pragma unroll
    for (int k = 0; k < N_SITES / 4 / THREADS; ++k) {
        xs4[tid + k * THREADS] = xrow[tid + k * THREADS];
    }
    if (tid < N_GRID) xs[N_SITES + tid] = 0.0f;
    __syncthreads();

    float acc = 0.0f;
#pragma unroll
    for (int k = 0; k < SITES_PER_THREAD; ++k) {
        const int i = tid + k * THREADS;
        const float xi = xs[i];
        const float u  = g_coef[i];
        const float jr = g_coef[N_SITES + i];
        const float jd = g_coef[2 * N_SITES + i];
        acc += xi * fmaf(jr, xs[i + 1], fmaf(jd, xs[i + N_GRID], u));
    }

    // Warp reduction
#pragma unroll
    for (int off = 16; off > 0; off >>= 1)
        acc += __shfl_down_sync(0xFFFFFFFFu, acc, off);

    if ((tid & 31) == 0) warp_sums[tid >> 5] = acc;
    __syncthreads();

    if (tid < 32) {
        float v = (tid < THREADS / 32) ? warp_sums[tid] : 0.0f;
#pragma unroll
        for (int off = 4; off > 0; off >>= 1)
            v += __shfl_down_sync(0xFFFFFFFFu, v, off);
        if (tid == 0) out[b] = v;
    }
}

extern "C" void kernel_launch(void* const* d_in, const int* in_sizes, int n_in,
                              void* d_out, int out_size) {
    const float* x      = (const float*)d_in[0];  // [512, 4096]
    const float* unary  = (const float*)d_in[1];  // [4096]
    const float* binary = (const float*)d_in[2];  // [4096, 4096]
    const float* mask   = (const float*)d_in[3];  // [4096, 4096]
    float* out = (float*)d_out;                   // [512]

    gather_coef_kernel<<<(N_SITES + THREADS - 1) / THREADS, THREADS>>>(unary, binary, mask);
    ising_energy_kernel<<<BATCH, THREADS>>>(x, out);
}